// round 15
// baseline (speedup 1.0000x reference)
#include <cuda_runtime.h>
#include <cstdint>

#define TN 32768
#define TLOOP 32799
#define NCHUNK 2050
#define NSTEPS (NCHUNK*16)   /* 32800 */
#define NBC 14
#define NACL 10
#define NACG 35
#define KACN 52
#define K0 20
#define K1 32
#define PADL 50              /* (K0-1)+(K1-1) */
#define XPLEN (TN + PADL)    /* 32818 */
#define RELSTRIDE 32832
#define FULLM 0xffffffffu

__device__ float g_xp[XPLEN];
__device__ float g_drive[NSTEPS*NBC];
__device__ float g_rel[2*NBC*RELSTRIDE];
__device__ float g_kbc[NBC*K0];
__device__ float g_kglu[K1];

__device__ __forceinline__ float ftanh(float x){
    float y; asm("tanh.approx.f32 %0, %1;" : "=f"(y) : "f"(x)); return y;
}
/* ---- packed fp32x2 ops (FFMA2 path, full fp32 precision) ---- */
__device__ __forceinline__ uint64_t pk(float lo, float hi){
    uint64_t r; asm("mov.b64 %0, {%1,%2};" : "=l"(r) : "f"(lo), "f"(hi)); return r;
}
__device__ __forceinline__ void upk(uint64_t v, float &lo, float &hi){
    asm("mov.b64 {%0,%1}, %2;" : "=f"(lo), "=f"(hi) : "l"(v));
}
__device__ __forceinline__ uint64_t fma2(uint64_t a, uint64_t b, uint64_t c){
    uint64_t d; asm("fma.rn.f32x2 %0, %1, %2, %3;" : "=l"(d) : "l"(a), "l"(b), "l"(c)); return d;
}
__device__ __forceinline__ uint64_t mul2(uint64_t a, uint64_t b){
    uint64_t d; asm("mul.rn.f32x2 %0, %1, %2;" : "=l"(d) : "l"(a), "l"(b)); return d;
}
__device__ __forceinline__ uint64_t add2(uint64_t a, uint64_t b){
    uint64_t d; asm("add.rn.f32x2 %0, %1, %2;" : "=l"(d) : "l"(a), "l"(b)); return d;
}
/* ---- ordered shared-memory ops (warp-synchronous broadcast, no barrier):
   producer STS sits at a warp-CONVERGED point (branch-free slot-select); the
   in-order smem pipe of a single warp guarantees later LDS sees it. The
   volatile asm order is preserved by the compiler, so the textual order of
   STS/LDS ops below is the SASS order — used deliberately to keep tanhH's
   MUFU+STS out of the q0..q15 commit path. ---- */
__device__ __forceinline__ void sts32(float* p, float v){
    uint32_t a = (uint32_t)__cvta_generic_to_shared(p);
    asm volatile("st.shared.f32 [%0], %1;" :: "r"(a), "f"(v) : "memory");
}
__device__ __forceinline__ uint64_t ld64sv(const float* p){
    uint32_t a = (uint32_t)__cvta_generic_to_shared(p);
    uint64_t r;
    asm volatile("ld.shared.b64 %0, [%1];" : "=l"(r) : "r"(a) : "memory");
    return r;
}
__device__ __forceinline__ void ld128sv(const float* p, uint64_t &a, uint64_t &b){
    uint32_t ad = (uint32_t)__cvta_generic_to_shared(p);
    asm volatile("ld.shared.v2.u64 {%0,%1}, [%2];" : "=l"(a), "=l"(b) : "r"(ad) : "memory");
}

// double-exponential AC kernel -> IIR coefficients (exact FIR-equivalent with
// truncation correction): kern(L) = A*r1^L - B*r2^L (L=0 newest), L2-normalized
__device__ __forceinline__ void ac_coef(float ltr, float ltd,
    float &A, float &B, float &r1, float &r2, float &c1, float &c2){
    float tr = expf(ltr), td = expf(ltd);
    float beta = (td + tr) / (td * tr);
    float n2 = 0.f;
    for (int k = 0; k < KACN; k++){
        float t = 0.8f - (float)k * (1.0f/64.0f);
        float v = expf(-t/td) - expf(-beta*t);
        n2 = fmaf(v, v, n2);
    }
    float inv = 1.0f / sqrtf(n2);
    const float c0 = 0.8f - 51.0f*(1.0f/64.0f);
    A  = expf(-c0/td) * inv;
    B  = expf(-beta*c0) * inv;
    r1 = expf(-1.0f/(64.0f*td));
    r2 = expf(-beta*(1.0f/64.0f));
    c1 = expf(-0.8125f/td);        /* r1^52 */
    c2 = expf(-beta*0.8125f);      /* r2^52 */
}

// ---------------- setup: BC biphasic kernels + iGluSnFR kernel ----------------
__global__ void setup_kernel(const float* __restrict__ lks){
    int t = threadIdx.x;
    if (t < NBC){
        float speed = expf(lks[t]);
        float ct = (t < 5) ? -1.0f : 1.0f;
        float vals[K0]; float n2 = 0.f;
        #pragma unroll
        for (int j = 0; j < K0; j++){
            float ts = (float)j * (1.0f/64.0f) * speed;
            float a = ts / 0.05f, b = ts / 0.1f;
            float v = a*a*expf(-a) - 0.8f*b*b*expf(-b);
            v *= ct;
            vals[j] = v; n2 += v*v;
        }
        float inv = 1.0f / sqrtf(n2);
        #pragma unroll
        for (int j = 0; j < K0; j++) g_kbc[t*K0+j] = vals[j]*inv;
    }
    if (t == 32){
        float vals[K1]; float s = 0.f;
        #pragma unroll
        for (int j = 0; j < K1; j++){
            float tg = (float)j * (1.0f/64.0f);
            float v = (1.0f - expf(-tg/0.02f)) * expf(-tg/0.1f);
            vals[j] = v; s += v;
        }
        #pragma unroll
        for (int j = 0; j < K1; j++) g_kglu[j] = vals[j]/s;
    }
}

// ---------------- stimulus affine + edge padding ----------------
__global__ void xp_kernel(const float* __restrict__ x,
                          const float* __restrict__ sb,
                          const float* __restrict__ ss){
    int i = blockIdx.x*blockDim.x + threadIdx.x;
    if (i >= XPLEN) return;
    float es = expf(ss[0]); float b = sb[0];
    int s = i - PADL; if (s < 0) s = 0;
    g_xp[i] = x[s]*es + b;
}

// ---------------- per-BC 20-tap FIR -> drive[NSTEPS][NBC] ----------------
__global__ void drive_kernel(){
    __shared__ float skb[NBC*K0];
    int tid = threadIdx.x;
    for (int i = tid; i < NBC*K0; i += blockDim.x) skb[i] = g_kbc[i];
    __syncthreads();
    int n = blockIdx.x*blockDim.x + tid;
    if (n >= NSTEPS) return;
    if (n >= TLOOP){
        #pragma unroll
        for (int c = 0; c < NBC; c++) g_drive[n*NBC+c] = 0.f;
        return;
    }
    float xw[K0];
    #pragma unroll
    for (int j = 0; j < K0; j++) xw[j] = g_xp[n + j];
    #pragma unroll
    for (int c = 0; c < NBC; c++){
        float a0 = 0.f, a1 = 0.f;
        #pragma unroll
        for (int j = 0; j < K0; j++){
            float w = skb[c*K0+j];
            float v = xw[K0-1-j];
            if (j & 1) a1 = fmaf(w, v, a1); else a0 = fmaf(w, v, a0);
        }
        g_drive[n*NBC+c] = a0 + a1;
    }
}

// ---------------- the sequential scan: 2 blocks (pathways) x 1 warp ----------------
__global__ void __launch_bounds__(32,1) scan_kernel(
    const float* __restrict__ P_sigoff, const float* __restrict__ P_lslope,
    const float* __restrict__ P_lp01,  const float* __restrict__ P_lp12,
    const float* __restrict__ P_lipc,  const float* __restrict__ P_lrrpc,
    const float* __restrict__ P_ipst,  const float* __restrict__ P_rrpst,
    const float* __restrict__ P_laclbc, const float* __restrict__ P_lbcacl,
    const float* __restrict__ P_acltr, const float* __restrict__ P_acltd,
    const float* __restrict__ P_aclsl, const float* __restrict__ P_aclof,
    const float* __restrict__ P_lacgbc, const float* __restrict__ P_lbcacg,
    const float* __restrict__ P_acgtr, const float* __restrict__ P_acgtd,
    const float* __restrict__ P_acgsl, const float* __restrict__ P_acgof,
    const float* __restrict__ P_laclacg, const float* __restrict__ P_bcnoff)
{
    const int path = blockIdx.x;
    const int l = threadIdx.x;
    __shared__ float ringA[11*53];          /* rows 0-9 ACL, row 10 dummy */
    __shared__ float ringG[NACG*53];
    __shared__ float dbuf[2][16*NBC];
    __shared__ __align__(16) float sm_B[48];   /* [0..34] tvG/tvH, [35]=0, [36..45] tvA, [46..47] dummy */
    __shared__ __align__(16) float sm_tvA[12]; /* LNR only; [10..11] dummy */
    __shared__ __align__(16) float sm_rel[48]; /* [0..13] rel, [14..15]=0, [16..47] scratch */
    for (int i = l; i < 11*53; i += 32) ringA[i] = 0.f;
    for (int i = l; i < NACG*53; i += 32) ringG[i] = 0.f;
    { if (l < 48) sm_B[l] = 0.f; if (l+32 < 48) sm_B[l+32] = 0.f; }
    if (l < 12) sm_tvA[l] = 0.f;
    { if (l < 48) sm_rel[l] = 0.f; if (l+32 < 48) sm_rel[l+32] = 0.f; }

    const bool prim = (l < NBC);
    const int bc = prim ? l : ((l >= 16 && l < 16+NBC) ? (l-16) : -1);
    const int relSlot = prim ? l : (16 + l);          /* scratch for idle lanes */

    // ---- BC pool role (prim lanes, both paths); tanh-form final sigmoid ----
    // p = 0.5 + 0.5*tanh(z/2); per-tap prefold mh = 0.25*slope, xi coeff mBC = 0.5*slope
    float cP=0.f, mBC=0.f, c_p01=0.f, c_p12=0.f, c_ipcap=0.f, c_irrp=0.f;
    float ip=0.f, rrp=0.f;
    float mh = 0.f;
    if (bc >= 0) mh = 0.25f*expf(P_lslope[bc]);
    if (prim){
        float off   = P_sigoff[l] + (path ? P_bcnoff[l] : 0.f);
        mBC = 2.0f*mh;
        c_p01   = expf(P_lp01[l]);
        c_p12   = expf(P_lp12[l]);
        c_ipcap = expf(P_lipc[l]);
        float rc = expf(P_lrrpc[l]);
        c_irrp = 1.0f / rc;
        ip  = c_ipcap / (1.0f + expf(-P_ipst[l]));
        rrp = rc      / (1.0f + expf(-P_rrpst[l]));
        float sA = 0.f, sG = 0.f;
        #pragma unroll
        for (int j = 0; j < NACL; j++) sA += -expf(P_laclbc[l*NACL+j]);
        if (path){
            #pragma unroll
            for (int j = 0; j < NACG; j++) sG += -expf(P_lacgbc[l*NACG+j]);
        }
        cP = mBC*(0.5f*(sA+sG) - off);
    }

    float* relrow = g_rel + (path*NBC + (prim ? l : 0))*RELSTRIDE;
    int ri = 0;

    float fd0,fd1,fd2,fd3,fd4,fd5,fd6;
#define LOADCHUNK(k) do{ const float* _p = g_drive + (k)*224 + l; \
        fd0=_p[0]; fd1=_p[32]; fd2=_p[64]; fd3=_p[96]; fd4=_p[128]; fd5=_p[160]; fd6=_p[192]; }while(0)
#define STORECHUNK(bi) do{ float* _q = dbuf[bi] + l; \
        _q[0]=fd0; _q[32]=fd1; _q[64]=fd2; _q[96]=fd3; _q[128]=fd4; _q[160]=fd5; _q[192]=fd6; }while(0)

    if (path == 0){
        // ================= LNR pathway (R14 form) =================
        uint64_t wA2[5];
        #pragma unroll
        for (int k = 0; k < 5; k++) wA2[k] = 0;
        if (prim){
            #pragma unroll
            for (int k = 0; k < 5; k++){
                float w0 = -expf(P_laclbc[l*NACL+2*k]);
                float w1 = -expf(P_laclbc[l*NACL+2*k+1]);
                wA2[k] = pk(mh*w0, mh*w1);
            }
        }
        uint64_t rA2p=0, nkAc2=0, kA12p=0, wyA2[7];
        float caA=0.f, dkA=0.f;
        #pragma unroll
        for (int k = 0; k < 7; k++) wyA2[k] = 0;
        if (l < NACL){
            float A,B,r1,r2,c1,c2;
            ac_coef(P_acltr[l], P_acltd[l], A,B,r1,r2,c1,c2);
            float ha = 0.5f*expf(P_aclsl[l]);
            float kA1 = ha*A, kA2 = ha*B;
            rA2p  = pk(r1, r2);
            nkAc2 = pk(-kA1*c1, -kA2*c2);
            kA12p = pk(kA1, kA2);
            caA = -ha*P_aclof[l];
            dkA = kA1 - kA2;
            #pragma unroll
            for (int k = 0; k < 7; k++)
                wyA2[k] = pk(expf(P_lbcacl[l*NBC+2*k]), expf(P_lbcacl[l*NBC+2*k+1]));
        }
        const int tvASlot = (l < NACL) ? l : 10;
        __syncwarp();
        uint64_t A12 = 0;
        float cvA = caA;
        { float tv0 = ftanh(cvA); sts32(sm_tvA + tvASlot, tv0); }
        LOADCHUNK(0); STORECHUNK(0); LOADCHUNK(1);
        __syncwarp();
        for (int c = 0; c < NCHUNK; c++){
            int cur = c & 1;
            STORECHUNK(cur^1);
            int nk = (c+2 < NCHUNK) ? (c+2) : (NCHUNK-1);
            LOADCHUNK(nk);
            __syncwarp();
            const float* db = dbuf[cur];
            int tbase = c*16;
            #pragma unroll 4
            for (int i = 0; i < 16; i++){
                uint64_t tp0, tp1, tp2, tp3, tp4;
                ld128sv(sm_tvA+0, tp0, tp1);
                ld128sv(sm_tvA+4, tp2, tp3);
                tp4 = ld64sv(sm_tvA+8);
                float yoA = (l < NACL) ? ringA[l*53+ri] : 0.f;
                float xi  = prim ? db[i*NBC + l] : 0.f;
                float fbBase = fmaf(mBC, xi, cP);
                float rrp_h = 0.5f*rrp;
                float t12 = c_p12*ip*(1.0f - rrp*c_irrp);
                float ip_n = ip + c_p01*(c_ipcap - ip) - t12;
                float rrp_m = rrp + t12;
                uint64_t pbA = fma2(nkAc2, pk(yoA,yoA), mul2(rA2p, A12));
                float bA1, bA2; upk(pbA, bA1, bA2);
                float bDA = (bA1 - bA2) + caA;
                uint64_t f0 = pk(fbBase, 0.f);
                uint64_t f1 = mul2(wA2[1], tp1);
                f0 = fma2(wA2[0], tp0, f0);
                f1 = fma2(wA2[2], tp2, f1);
                f0 = fma2(wA2[3], tp3, f0);
                f1 = fma2(wA2[4], tp4, f1);
                uint64_t fs = add2(f0, f1);
                float a0,a1; upk(fs,a0,a1);
                float tvp = ftanh(a0+a1);
                float relv = fmaf(rrp_h, tvp, rrp_h);
                ip = ip_n; rrp = rrp_m - relv;
                sts32(sm_rel + relSlot, relv);
                uint64_t rp0,rp1,rp2,rp3,rp4,rp5,rp6,rpx;
                ld128sv(sm_rel+0, rp0, rp1);
                ld128sv(sm_rel+4, rp2, rp3);
                ld128sv(sm_rel+8, rp4, rp5);
                ld128sv(sm_rel+12, rp6, rpx);
                if (prim) relrow[tbase+i] = relv;       /* STG off the chain */
                uint64_t y0 = mul2(wyA2[0], rp0);
                uint64_t y1 = mul2(wyA2[1], rp1);
                y0 = fma2(wyA2[2], rp2, y0);
                y1 = fma2(wyA2[3], rp3, y1);
                y0 = fma2(wyA2[4], rp4, y0);
                y1 = fma2(wyA2[5], rp5, y1);
                y0 = fma2(wyA2[6], rp6, y0);
                uint64_t ys = add2(y0, y1);
                float v0,v1; upk(ys,v0,v1);
                float yA = v0+v1;
                cvA = fmaf(dkA, yA, bDA);
                float tvA = ftanh(cvA);
                sts32(sm_tvA + tvASlot, tvA);
                if (l < NACL) ringA[l*53+ri] = yA;
                A12 = fma2(kA12p, pk(yA,yA), pbA);
                ri = (ri == KACN-1) ? 0 : ri+1;
            }
            __syncwarp();
        }
    } else {
        // ===== BCN pathway: R14 + tanhH out of the q-commit path, unroll 2 =====
        const bool isA = (l >= 16 && l < 26);
        const bool isH = (l < 3);
        // ---- G channel (every lane owns ACG channel l) ----
        uint64_t rG2p, nkGc2, kG12p, wGa2[5], wyG2[7];
        float cgG, dkG;
        {
            float A,B,r1,r2,c1,c2;
            ac_coef(P_acgtr[l], P_acgtd[l], A,B,r1,r2,c1,c2);
            float hg = 0.5f*expf(P_acgsl[l]);
            float k1 = hg*A, k2 = hg*B;
            rG2p  = pk(r1, r2);
            nkGc2 = pk(-k1*c1, -k2*c2);
            kG12p = pk(k1, k2);
            dkG = k1 - k2;
            float sw = 0.f;
            #pragma unroll
            for (int k = 0; k < 5; k++){
                float w0 = -expf(P_laclacg[l*NACL+2*k]);
                float w1 = -expf(P_laclacg[l*NACL+2*k+1]);
                sw += w0 + w1;
                wGa2[k] = pk(hg*0.5f*w0, hg*0.5f*w1);
            }
            cgG = hg*(0.5f*sw - P_acgof[l]);
            #pragma unroll
            for (int k = 0; k < 7; k++)
                wyG2[k] = pk(expf(P_lbcacg[l*NBC+2*k]), expf(P_lbcacg[l*NBC+2*k+1]));
        }
        // ---- Sec channel: A on lanes 16-25, H(=ACG 32-34) on lanes 0-2 ----
        uint64_t rS2p=0, nkSc2=0, kS12p=0, wyS2[7], wHa2[5];
        float cS=0.f, dkS=0.f;
        float* secPtr = ringA + 10*53;
        #pragma unroll
        for (int k = 0; k < 7; k++) wyS2[k] = 0;
        #pragma unroll
        for (int k = 0; k < 5; k++) wHa2[k] = 0;
        if (isA){
            int a = l - 16;
            float A,B,r1,r2,c1,c2;
            ac_coef(P_acltr[a], P_acltd[a], A,B,r1,r2,c1,c2);
            float ha = 0.5f*expf(P_aclsl[a]);
            float k1 = ha*A, k2 = ha*B;
            rS2p = pk(r1,r2); nkSc2 = pk(-k1*c1,-k2*c2); kS12p = pk(k1,k2);
            dkS = k1 - k2;
            cS = -ha*P_aclof[a];
            #pragma unroll
            for (int k = 0; k < 7; k++)
                wyS2[k] = pk(expf(P_lbcacl[a*NBC+2*k]), expf(P_lbcacl[a*NBC+2*k+1]));
            secPtr = ringA + a*53;
        } else if (isH){
            int h = l + 32;
            float A,B,r1,r2,c1,c2;
            ac_coef(P_acgtr[h], P_acgtd[h], A,B,r1,r2,c1,c2);
            float hh = 0.5f*expf(P_acgsl[h]);
            float k1 = hh*A, k2 = hh*B;
            rS2p = pk(r1,r2); nkSc2 = pk(-k1*c1,-k2*c2); kS12p = pk(k1,k2);
            dkS = k1 - k2;
            float swh = 0.f;
            #pragma unroll
            for (int k = 0; k < 5; k++){
                float w0 = -expf(P_laclacg[h*NACL+2*k]);
                float w1 = -expf(P_laclacg[h*NACL+2*k+1]);
                swh += w0 + w1;
                wHa2[k] = pk(hh*0.5f*w0, hh*0.5f*w1);
            }
            cS = hh*(0.5f*swh - P_acgof[h]);
            #pragma unroll
            for (int k = 0; k < 7; k++)
                wyS2[k] = pk(expf(P_lbcacg[h*NBC+2*k]), expf(P_lbcacg[h*NBC+2*k+1]));
            secPtr = ringG + h*53;
        }
        const int secSlot = isA ? (36 + (l-16)) : 46;
        const int hSlot   = isH ? (32 + l) : 46;
        // ---- BC feedback: 36 ACG taps (35+pad) + 10 ACL taps, prim lanes ----
        uint64_t wFB[18], wA2[5];
        #pragma unroll
        for (int k = 0; k < 18; k++) wFB[k] = 0;
        #pragma unroll
        for (int k = 0; k < 5; k++) wA2[k] = 0;
        if (prim){
            #pragma unroll
            for (int k = 0; k < 18; k++){
                int j0 = 2*k, j1 = 2*k+1;
                float w0 = (j0 < NACG) ? mh*(-expf(P_lacgbc[l*NACG+j0])) : 0.f;
                float w1 = (j1 < NACG) ? mh*(-expf(P_lacgbc[l*NACG+j1])) : 0.f;
                wFB[k] = pk(w0, w1);
            }
            #pragma unroll
            for (int k = 0; k < 5; k++){
                float w0 = -expf(P_laclbc[l*NACL+2*k]);
                float w1 = -expf(P_laclbc[l*NACL+2*k+1]);
                wA2[k] = pk(mh*w0, mh*w1);
            }
        }
        float* gRow = ringG + l*53;
        __syncwarp();

        uint64_t S12 = 0;
        float cvS = cS;
        /* carried state for relocated yG: rel regs, pbG, bDG, prev ring idx */
        uint64_t rp0c=0,rp1c=0,rp2c=0,rp3c=0,rp4c=0,rp5c=0,rp6c=0;
        uint64_t pbG_c = 0;
        float bDG_c = cgG;
        int ri_c = 0;
        { float tv0 = ftanh(cvS); sts32(sm_B + secSlot, tv0); }
        LOADCHUNK(0); STORECHUNK(0); LOADCHUNK(1);
        __syncwarp();
        for (int c = 0; c < NCHUNK; c++){
            int cur = c & 1;
            STORECHUNK(cur^1);
            int nk = (c+2 < NCHUNK) ? (c+2) : (NCHUNK-1);
            LOADCHUNK(nk);
            __syncwarp();
            const float* db = dbuf[cur];
            int tbase = c*16;
            #pragma unroll 2
            for (int i = 0; i < 16; i++){
                /* ---- head: tvA LDS opens; relocated yG fills its shadow ---- */
                uint64_t t0,t1,t2,t3,t4;
                ld128sv(sm_B+36, t0, t1);
                ld128sv(sm_B+40, t2, t3);
                t4 = ld64sv(sm_B+44);
                uint64_t ga = mul2(wyG2[0], rp0c);
                uint64_t gb = mul2(wyG2[1], rp1c);
                ga = fma2(wyG2[2], rp2c, ga);
                gb = fma2(wyG2[3], rp3c, gb);
                ga = fma2(wyG2[4], rp4c, ga);
                gb = fma2(wyG2[5], rp5c, gb);
                ga = fma2(wyG2[6], rp6c, ga);
                uint64_t gsum = add2(ga, gb);
                float gv0,gv1; upk(gsum,gv0,gv1);
                float yG = gv0+gv1;
                gRow[ri_c] = yG;
                uint64_t G12 = fma2(kG12p, pk(yG,yG), pbG_c);
                float baseG = fmaf(dkG, yG, bDG_c);
                /* ---- this step's top ---- */
                float yoS = secPtr[ri];
                float yoG = gRow[ri];
                float xi  = prim ? db[i*NBC + l] : 0.f;
                float fbBase = fmaf(mBC, xi, cP);
                float rrp_h = 0.5f*rrp;
                float t12 = c_p12*ip*(1.0f - rrp*c_irrp);
                float ip_n = ip + c_p01*(c_ipcap - ip) - t12;
                float rrp_m = rrp + t12;
                uint64_t pbS = fma2(nkSc2, pk(yoS,yoS), mul2(rS2p, S12));
                uint64_t pbG = fma2(nkGc2, pk(yoG,yoG), mul2(rG2p, G12));
                float b1,b2; upk(pbS,b1,b2); float bDS = (b1-b2)+cS;
                upk(pbG,b1,b2); float bDG = (b1-b2)+cgG;
                /* ---- stage 2: ACG pre-activations from tvA ---- */
                uint64_t pg0 = pk(baseG, 0.f);
                uint64_t pg1 = mul2(wGa2[1], t1);
                pg0 = fma2(wGa2[0], t0, pg0);
                pg1 = fma2(wGa2[2], t2, pg1);
                pg0 = fma2(wGa2[3], t3, pg0);
                pg1 = fma2(wGa2[4], t4, pg1);
                uint64_t ph0 = pk(cvS, 0.f);
                uint64_t ph1 = mul2(wHa2[1], t1);
                ph0 = fma2(wHa2[0], t0, ph0);
                ph1 = fma2(wHa2[2], t2, ph1);
                ph0 = fma2(wHa2[3], t3, ph0);
                ph1 = fma2(wHa2[4], t4, ph1);
                uint64_t pgs = add2(pg0, pg1);
                float x0,x1;
                upk(pgs,x0,x1);
                /* tanhG + STS(tvG) FIRST, then issue tvG-only q loads,
                   THEN tanhH+STS(tvH), then q16/q17 — keeps tanhH's MUFU
                   and its STS out of the q0..q15 commit path. */
                float tvG = ftanh(x0+x1);
                sts32(sm_B + l, tvG);                   /* converged */
                uint64_t q0,q1,q2,q3,q4,q5,q6,q7,q8,q9,q10,q11,q12,q13,q14,q15,q16,q17;
                ld128sv(sm_B+0,  q0,  q1);
                ld128sv(sm_B+4,  q2,  q3);
                ld128sv(sm_B+8,  q4,  q5);
                ld128sv(sm_B+12, q6,  q7);
                ld128sv(sm_B+16, q8,  q9);
                ld128sv(sm_B+20, q10, q11);
                ld128sv(sm_B+24, q12, q13);
                ld128sv(sm_B+28, q14, q15);
                uint64_t phs = add2(ph0, ph1);
                upk(phs,x0,x1);
                float tvH = ftanh(x0+x1);
                sts32(sm_B + hSlot, tvH);               /* converged */
                ld128sv(sm_B+32, q16, q17);
                /* ACL->BC partials from t regs (fills the commit window) */
                uint64_t ae0 = mul2(wA2[0], t0);
                uint64_t ae1 = mul2(wA2[1], t1);
                ae0 = fma2(wA2[2], t2, ae0);
                ae1 = fma2(wA2[3], t3, ae1);
                ae0 = fma2(wA2[4], t4, ae0);
                /* ---- stage 3: 18 packed taps, 4 accums ---- */
                uint64_t s0 = pk(fbBase, 0.f);
                uint64_t s1 = ae0;
                uint64_t s2 = ae1;
                uint64_t s3 = mul2(wFB[3], q3);
                s0 = fma2(wFB[0], q0, s0);
                s1 = fma2(wFB[1], q1, s1);
                s2 = fma2(wFB[2], q2, s2);
                s0 = fma2(wFB[4], q4, s0);
                s1 = fma2(wFB[5], q5, s1);
                s2 = fma2(wFB[6], q6, s2);
                s3 = fma2(wFB[7], q7, s3);
                s0 = fma2(wFB[8], q8, s0);
                s1 = fma2(wFB[9], q9, s1);
                s2 = fma2(wFB[10], q10, s2);
                s3 = fma2(wFB[11], q11, s3);
                s0 = fma2(wFB[12], q12, s0);
                s1 = fma2(wFB[13], q13, s1);
                s2 = fma2(wFB[14], q14, s2);
                s3 = fma2(wFB[15], q15, s3);
                s0 = fma2(wFB[16], q16, s0);
                s1 = fma2(wFB[17], q17, s1);
                uint64_t sv = add2(add2(s0,s1), add2(s2,s3));
                float u0,u1; upk(sv,u0,u1);
                float tvp = ftanh(u0+u1);
                float relv = fmaf(rrp_h, tvp, rrp_h);
                ip = ip_n; rrp = rrp_m - relv;
                sts32(sm_rel + relSlot, relv);          /* converged */
                /* ---- tail: rel LDS first; STG after; yS matvec; tanhS early ---- */
                uint64_t rpx;
                ld128sv(sm_rel+0, rp0c, rp1c);
                ld128sv(sm_rel+4, rp2c, rp3c);
                ld128sv(sm_rel+8, rp4c, rp5c);
                ld128sv(sm_rel+12, rp6c, rpx);
                if (prim) relrow[tbase+i] = relv;       /* STG off the chain */
                uint64_t sa = mul2(wyS2[0], rp0c);
                uint64_t sb = mul2(wyS2[1], rp1c);
                sa = fma2(wyS2[2], rp2c, sa);
                sb = fma2(wyS2[3], rp3c, sb);
                sa = fma2(wyS2[4], rp4c, sa);
                sb = fma2(wyS2[5], rp5c, sb);
                sa = fma2(wyS2[6], rp6c, sa);
                uint64_t ss2 = add2(sa, sb);
                float v0,v1; upk(ss2,v0,v1);
                float yS = v0+v1;
                cvS = fmaf(dkS, yS, bDS);
                /* chain first: tanh + STS immediately after cvS */
                float tvS = ftanh(cvS);
                sts32(sm_B + secSlot, tvS);
                secPtr[ri] = yS;
                S12 = fma2(kS12p, pk(yS,yS), pbS);
                pbG_c = pbG; bDG_c = bDG; ri_c = ri;
                ri = (ri == KACN-1) ? 0 : ri+1;
            }
            __syncwarp();
        }
    }
#undef LOADCHUNK
#undef STORECHUNK
}

// ---------------- iGluSnFR readout: 32-tap FIR over rel ----------------
__global__ void out_kernel(float* __restrict__ out){
    __shared__ float skg[K1];
    int tid = threadIdx.x;
    if (tid < K1) skg[tid] = g_kglu[tid];
    __syncthreads();
    int oid = blockIdx.x*blockDim.x + tid;
    if (oid >= 2*NBC*TN) return;
    int n  = oid & (TN-1);
    int pc = oid >> 15;
    const float* r = g_rel + pc*RELSTRIDE + n;
    float a0 = 0.f, a1 = 0.f;
    #pragma unroll
    for (int j = 0; j < K1; j++){
        float v = r[K1-1-j];
        if (j & 1) a1 = fmaf(skg[j], v, a1);
        else       a0 = fmaf(skg[j], v, a0);
    }
    out[oid] = a0 + a1;
}

extern "C" void kernel_launch(void* const* d_in, const int* in_sizes, int n_in,
                              void* d_out, int out_size){
    (void)in_sizes; (void)n_in; (void)out_size;
    const float* x  = (const float*)d_in[0];
    const float* sb = (const float*)d_in[1];
    const float* ss = (const float*)d_in[2];

    setup_kernel<<<1, 64>>>((const float*)d_in[3]);
    xp_kernel<<<(XPLEN+255)/256, 256>>>(x, sb, ss);
    drive_kernel<<<(NSTEPS+127)/128, 128>>>();
    scan_kernel<<<2, 32>>>(
        (const float*)d_in[4],  (const float*)d_in[5],
        (const float*)d_in[6],  (const float*)d_in[7],
        (const float*)d_in[8],  (const float*)d_in[9],
        (const float*)d_in[10], (const float*)d_in[11],
        (const float*)d_in[12], (const float*)d_in[13],
        (const float*)d_in[14], (const float*)d_in[15],
        (const float*)d_in[16], (const float*)d_in[17],
        (const float*)d_in[18], (const float*)d_in[19],
        (const float*)d_in[20], (const float*)d_in[21],
        (const float*)d_in[22], (const float*)d_in[23],
        (const float*)d_in[24], (const float*)d_in[25]);
    out_kernel<<<(2*NBC*TN+255)/256, 256>>>((float*)d_out);
}

// round 16
// speedup vs baseline: 1.0281x; 1.0281x over previous
#include <cuda_runtime.h>
#include <cstdint>

#define TN 32768
#define TLOOP 32799
#define NCHUNK 2050
#define NSTEPS (NCHUNK*16)   /* 32800 */
#define NBC 14
#define NACL 10
#define NACG 35
#define KACN 52
#define K0 20
#define K1 32
#define PADL 50              /* (K0-1)+(K1-1) */
#define XPLEN (TN + PADL)    /* 32818 */
#define RELSTRIDE 32832
#define FULLM 0xffffffffu

__device__ float g_xp[XPLEN];
__device__ float g_drive[NSTEPS*NBC];
__device__ float g_rel[2*NBC*RELSTRIDE];
__device__ float g_kbc[NBC*K0];
__device__ float g_kglu[K1];

__device__ __forceinline__ float ftanh(float x){
    float y; asm("tanh.approx.f32 %0, %1;" : "=f"(y) : "f"(x)); return y;
}
/* ---- packed fp32x2 ops (FFMA2 path, full fp32 precision) ---- */
__device__ __forceinline__ uint64_t pk(float lo, float hi){
    uint64_t r; asm("mov.b64 %0, {%1,%2};" : "=l"(r) : "f"(lo), "f"(hi)); return r;
}
__device__ __forceinline__ void upk(uint64_t v, float &lo, float &hi){
    asm("mov.b64 {%0,%1}, %2;" : "=f"(lo), "=f"(hi) : "l"(v));
}
__device__ __forceinline__ uint64_t fma2(uint64_t a, uint64_t b, uint64_t c){
    uint64_t d; asm("fma.rn.f32x2 %0, %1, %2, %3;" : "=l"(d) : "l"(a), "l"(b), "l"(c)); return d;
}
__device__ __forceinline__ uint64_t mul2(uint64_t a, uint64_t b){
    uint64_t d; asm("mul.rn.f32x2 %0, %1, %2;" : "=l"(d) : "l"(a), "l"(b)); return d;
}
__device__ __forceinline__ uint64_t add2(uint64_t a, uint64_t b){
    uint64_t d; asm("add.rn.f32x2 %0, %1, %2;" : "=l"(d) : "l"(a), "l"(b)); return d;
}
/* ---- ordered shared-memory ops (warp-synchronous broadcast, no barrier):
   producer STS sits at a warp-CONVERGED point (branch-free slot-select); the
   in-order smem pipe of a single warp guarantees later LDS sees it. The
   volatile asm textual order is the SASS order — exploited so each LDS only
   waits on the commits it actually needs (H-first staging below), and so the
   tvA STS is the LAST store before the next head's tvA LDS. ---- */
__device__ __forceinline__ void sts32(float* p, float v){
    uint32_t a = (uint32_t)__cvta_generic_to_shared(p);
    asm volatile("st.shared.f32 [%0], %1;" :: "r"(a), "f"(v) : "memory");
}
__device__ __forceinline__ uint64_t ld64sv(const float* p){
    uint32_t a = (uint32_t)__cvta_generic_to_shared(p);
    uint64_t r;
    asm volatile("ld.shared.b64 %0, [%1];" : "=l"(r) : "r"(a) : "memory");
    return r;
}
__device__ __forceinline__ void ld128sv(const float* p, uint64_t &a, uint64_t &b){
    uint32_t ad = (uint32_t)__cvta_generic_to_shared(p);
    asm volatile("ld.shared.v2.u64 {%0,%1}, [%2];" : "=l"(a), "=l"(b) : "r"(ad) : "memory");
}

// double-exponential AC kernel -> IIR coefficients (exact FIR-equivalent with
// truncation correction): kern(L) = A*r1^L - B*r2^L (L=0 newest), L2-normalized
__device__ __forceinline__ void ac_coef(float ltr, float ltd,
    float &A, float &B, float &r1, float &r2, float &c1, float &c2){
    float tr = expf(ltr), td = expf(ltd);
    float beta = (td + tr) / (td * tr);
    float n2 = 0.f;
    for (int k = 0; k < KACN; k++){
        float t = 0.8f - (float)k * (1.0f/64.0f);
        float v = expf(-t/td) - expf(-beta*t);
        n2 = fmaf(v, v, n2);
    }
    float inv = 1.0f / sqrtf(n2);
    const float c0 = 0.8f - 51.0f*(1.0f/64.0f);
    A  = expf(-c0/td) * inv;
    B  = expf(-beta*c0) * inv;
    r1 = expf(-1.0f/(64.0f*td));
    r2 = expf(-beta*(1.0f/64.0f));
    c1 = expf(-0.8125f/td);        /* r1^52 */
    c2 = expf(-beta*0.8125f);      /* r2^52 */
}

// ---------------- setup: BC biphasic kernels + iGluSnFR kernel ----------------
__global__ void setup_kernel(const float* __restrict__ lks){
    int t = threadIdx.x;
    if (t < NBC){
        float speed = expf(lks[t]);
        float ct = (t < 5) ? -1.0f : 1.0f;
        float vals[K0]; float n2 = 0.f;
        #pragma unroll
        for (int j = 0; j < K0; j++){
            float ts = (float)j * (1.0f/64.0f) * speed;
            float a = ts / 0.05f, b = ts / 0.1f;
            float v = a*a*expf(-a) - 0.8f*b*b*expf(-b);
            v *= ct;
            vals[j] = v; n2 += v*v;
        }
        float inv = 1.0f / sqrtf(n2);
        #pragma unroll
        for (int j = 0; j < K0; j++) g_kbc[t*K0+j] = vals[j]*inv;
    }
    if (t == 32){
        float vals[K1]; float s = 0.f;
        #pragma unroll
        for (int j = 0; j < K1; j++){
            float tg = (float)j * (1.0f/64.0f);
            float v = (1.0f - expf(-tg/0.02f)) * expf(-tg/0.1f);
            vals[j] = v; s += v;
        }
        #pragma unroll
        for (int j = 0; j < K1; j++) g_kglu[j] = vals[j]/s;
    }
}

// ---------------- stimulus affine + edge padding ----------------
__global__ void xp_kernel(const float* __restrict__ x,
                          const float* __restrict__ sb,
                          const float* __restrict__ ss){
    int i = blockIdx.x*blockDim.x + threadIdx.x;
    if (i >= XPLEN) return;
    float es = expf(ss[0]); float b = sb[0];
    int s = i - PADL; if (s < 0) s = 0;
    g_xp[i] = x[s]*es + b;
}

// ---------------- per-BC 20-tap FIR -> drive[NSTEPS][NBC] ----------------
__global__ void drive_kernel(){
    __shared__ float skb[NBC*K0];
    int tid = threadIdx.x;
    for (int i = tid; i < NBC*K0; i += blockDim.x) skb[i] = g_kbc[i];
    __syncthreads();
    int n = blockIdx.x*blockDim.x + tid;
    if (n >= NSTEPS) return;
    if (n >= TLOOP){
        #pragma unroll
        for (int c = 0; c < NBC; c++) g_drive[n*NBC+c] = 0.f;
        return;
    }
    float xw[K0];
    #pragma unroll
    for (int j = 0; j < K0; j++) xw[j] = g_xp[n + j];
    #pragma unroll
    for (int c = 0; c < NBC; c++){
        float a0 = 0.f, a1 = 0.f;
        #pragma unroll
        for (int j = 0; j < K0; j++){
            float w = skb[c*K0+j];
            float v = xw[K0-1-j];
            if (j & 1) a1 = fmaf(w, v, a1); else a0 = fmaf(w, v, a0);
        }
        g_drive[n*NBC+c] = a0 + a1;
    }
}

// ---------------- the sequential scan: 2 blocks (pathways) x 1 warp ----------------
__global__ void __launch_bounds__(32,1) scan_kernel(
    const float* __restrict__ P_sigoff, const float* __restrict__ P_lslope,
    const float* __restrict__ P_lp01,  const float* __restrict__ P_lp12,
    const float* __restrict__ P_lipc,  const float* __restrict__ P_lrrpc,
    const float* __restrict__ P_ipst,  const float* __restrict__ P_rrpst,
    const float* __restrict__ P_laclbc, const float* __restrict__ P_lbcacl,
    const float* __restrict__ P_acltr, const float* __restrict__ P_acltd,
    const float* __restrict__ P_aclsl, const float* __restrict__ P_aclof,
    const float* __restrict__ P_lacgbc, const float* __restrict__ P_lbcacg,
    const float* __restrict__ P_acgtr, const float* __restrict__ P_acgtd,
    const float* __restrict__ P_acgsl, const float* __restrict__ P_acgof,
    const float* __restrict__ P_laclacg, const float* __restrict__ P_bcnoff)
{
    const int path = blockIdx.x;
    const int l = threadIdx.x;
    __shared__ float ringA[11*53];          /* rows 0-9 ACL, row 10 dummy */
    __shared__ float ringG[NACG*53];
    __shared__ float dbuf[2][16*NBC];
    __shared__ __align__(16) float sm_B[48];   /* [0..34] tvG/tvH, [35]=0, [36..45] tvA, [46..47] dummy */
    __shared__ __align__(16) float sm_tvA[12]; /* LNR only; [10..11] dummy */
    __shared__ __align__(16) float sm_rel[48]; /* [0..13] rel, [14..15]=0, [16..47] scratch */
    for (int i = l; i < 11*53; i += 32) ringA[i] = 0.f;
    for (int i = l; i < NACG*53; i += 32) ringG[i] = 0.f;
    { if (l < 48) sm_B[l] = 0.f; if (l+32 < 48) sm_B[l+32] = 0.f; }
    if (l < 12) sm_tvA[l] = 0.f;
    { if (l < 48) sm_rel[l] = 0.f; if (l+32 < 48) sm_rel[l+32] = 0.f; }

    const bool prim = (l < NBC);
    const int bc = prim ? l : ((l >= 16 && l < 16+NBC) ? (l-16) : -1);
    const int relSlot = prim ? l : (16 + l);          /* scratch for idle lanes */

    // ---- BC pool role (prim lanes, both paths); tanh-form final sigmoid ----
    // p = 0.5 + 0.5*tanh(z/2); per-tap prefold mh = 0.25*slope, xi coeff mBC = 0.5*slope
    float cP=0.f, mBC=0.f, c_p01=0.f, c_p12=0.f, c_ipcap=0.f, c_irrp=0.f;
    float ip=0.f, rrp=0.f;
    float mh = 0.f;
    if (bc >= 0) mh = 0.25f*expf(P_lslope[bc]);
    if (prim){
        float off   = P_sigoff[l] + (path ? P_bcnoff[l] : 0.f);
        mBC = 2.0f*mh;
        c_p01   = expf(P_lp01[l]);
        c_p12   = expf(P_lp12[l]);
        c_ipcap = expf(P_lipc[l]);
        float rc = expf(P_lrrpc[l]);
        c_irrp = 1.0f / rc;
        ip  = c_ipcap / (1.0f + expf(-P_ipst[l]));
        rrp = rc      / (1.0f + expf(-P_rrpst[l]));
        float sA = 0.f, sG = 0.f;
        #pragma unroll
        for (int j = 0; j < NACL; j++) sA += -expf(P_laclbc[l*NACL+j]);
        if (path){
            #pragma unroll
            for (int j = 0; j < NACG; j++) sG += -expf(P_lacgbc[l*NACG+j]);
        }
        cP = mBC*(0.5f*(sA+sG) - off);
    }

    float* relrow = g_rel + (path*NBC + (prim ? l : 0))*RELSTRIDE;
    int ri = 0;

    float fd0,fd1,fd2,fd3,fd4,fd5,fd6;
#define LOADCHUNK(k) do{ const float* _p = g_drive + (k)*224 + l; \
        fd0=_p[0]; fd1=_p[32]; fd2=_p[64]; fd3=_p[96]; fd4=_p[128]; fd5=_p[160]; fd6=_p[192]; }while(0)
#define STORECHUNK(bi) do{ float* _q = dbuf[bi] + l; \
        _q[0]=fd0; _q[32]=fd1; _q[64]=fd2; _q[96]=fd3; _q[128]=fd4; _q[160]=fd5; _q[192]=fd6; }while(0)

    if (path == 0){
        // ================= LNR pathway (K-best / R11 form) =================
        uint64_t wA2[5];
        #pragma unroll
        for (int k = 0; k < 5; k++) wA2[k] = 0;
        if (prim){
            #pragma unroll
            for (int k = 0; k < 5; k++){
                float w0 = -expf(P_laclbc[l*NACL+2*k]);
                float w1 = -expf(P_laclbc[l*NACL+2*k+1]);
                wA2[k] = pk(mh*w0, mh*w1);
            }
        }
        uint64_t rA2p=0, nkAc2=0, kA12p=0, wyA2[7];
        float caA=0.f, dkA=0.f;
        #pragma unroll
        for (int k = 0; k < 7; k++) wyA2[k] = 0;
        if (l < NACL){
            float A,B,r1,r2,c1,c2;
            ac_coef(P_acltr[l], P_acltd[l], A,B,r1,r2,c1,c2);
            float ha = 0.5f*expf(P_aclsl[l]);
            float kA1 = ha*A, kA2 = ha*B;
            rA2p  = pk(r1, r2);
            nkAc2 = pk(-kA1*c1, -kA2*c2);
            kA12p = pk(kA1, kA2);
            caA = -ha*P_aclof[l];
            dkA = kA1 - kA2;
            #pragma unroll
            for (int k = 0; k < 7; k++)
                wyA2[k] = pk(expf(P_lbcacl[l*NBC+2*k]), expf(P_lbcacl[l*NBC+2*k+1]));
        }
        const int tvASlot = (l < NACL) ? l : 10;
        __syncwarp();
        uint64_t A12 = 0;
        float cvA = caA;
        { float tv0 = ftanh(cvA); sts32(sm_tvA + tvASlot, tv0); }
        LOADCHUNK(0); STORECHUNK(0); LOADCHUNK(1);
        __syncwarp();
        for (int c = 0; c < NCHUNK; c++){
            int cur = c & 1;
            STORECHUNK(cur^1);
            int nk = (c+2 < NCHUNK) ? (c+2) : (NCHUNK-1);
            LOADCHUNK(nk);
            __syncwarp();
            const float* db = dbuf[cur];
            int tbase = c*16;
            #pragma unroll 4
            for (int i = 0; i < 16; i++){
                uint64_t tp0, tp1, tp2, tp3, tp4;
                ld128sv(sm_tvA+0, tp0, tp1);
                ld128sv(sm_tvA+4, tp2, tp3);
                tp4 = ld64sv(sm_tvA+8);
                float yoA = (l < NACL) ? ringA[l*53+ri] : 0.f;
                float xi  = prim ? db[i*NBC + l] : 0.f;
                float fbBase = fmaf(mBC, xi, cP);
                float rrp_h = 0.5f*rrp;
                float t12 = c_p12*ip*(1.0f - rrp*c_irrp);
                float ip_n = ip + c_p01*(c_ipcap - ip) - t12;
                float rrp_m = rrp + t12;
                uint64_t pbA = fma2(nkAc2, pk(yoA,yoA), mul2(rA2p, A12));
                float bA1, bA2; upk(pbA, bA1, bA2);
                float bDA = (bA1 - bA2) + caA;
                uint64_t f0 = pk(fbBase, 0.f);
                uint64_t f1 = mul2(wA2[1], tp1);
                f0 = fma2(wA2[0], tp0, f0);
                f1 = fma2(wA2[2], tp2, f1);
                f0 = fma2(wA2[3], tp3, f0);
                f1 = fma2(wA2[4], tp4, f1);
                uint64_t fs = add2(f0, f1);
                float a0,a1; upk(fs,a0,a1);
                float tvp = ftanh(a0+a1);
                float relv = fmaf(rrp_h, tvp, rrp_h);
                ip = ip_n; rrp = rrp_m - relv;
                sts32(sm_rel + relSlot, relv);
                if (prim) relrow[tbase+i] = relv;
                uint64_t rp0,rp1,rp2,rp3,rp4,rp5,rp6,rpx;
                ld128sv(sm_rel+0, rp0, rp1);
                ld128sv(sm_rel+4, rp2, rp3);
                ld128sv(sm_rel+8, rp4, rp5);
                ld128sv(sm_rel+12, rp6, rpx);
                uint64_t y0 = mul2(wyA2[0], rp0);
                uint64_t y1 = mul2(wyA2[1], rp1);
                y0 = fma2(wyA2[2], rp2, y0);
                y1 = fma2(wyA2[3], rp3, y1);
                y0 = fma2(wyA2[4], rp4, y0);
                y1 = fma2(wyA2[5], rp5, y1);
                y0 = fma2(wyA2[6], rp6, y0);
                uint64_t ys = add2(y0, y1);
                float v0,v1; upk(ys,v0,v1);
                float yA = v0+v1;
                cvA = fmaf(dkA, yA, bDA);
                if (l < NACL) ringA[l*53+ri] = yA;
                A12 = fma2(kA12p, pk(yA,yA), pbA);
                /* tvA STS is the LAST store before next head's LDS */
                float tvA = ftanh(cvA);
                sts32(sm_tvA + tvASlot, tvA);
                ri = (ri == KACN-1) ? 0 : ri+1;
            }
            __syncwarp();
        }
    } else {
        // ===== BCN pathway: K-best + H-first stage 2/3 =====
        const bool isA = (l >= 16 && l < 26);
        const bool isH = (l < 3);
        // ---- G channel (every lane owns ACG channel l) ----
        uint64_t rG2p, nkGc2, kG12p, wGa2[5], wyG2[7];
        float cgG, dkG;
        {
            float A,B,r1,r2,c1,c2;
            ac_coef(P_acgtr[l], P_acgtd[l], A,B,r1,r2,c1,c2);
            float hg = 0.5f*expf(P_acgsl[l]);
            float k1 = hg*A, k2 = hg*B;
            rG2p  = pk(r1, r2);
            nkGc2 = pk(-k1*c1, -k2*c2);
            kG12p = pk(k1, k2);
            dkG = k1 - k2;
            float sw = 0.f;
            #pragma unroll
            for (int k = 0; k < 5; k++){
                float w0 = -expf(P_laclacg[l*NACL+2*k]);
                float w1 = -expf(P_laclacg[l*NACL+2*k+1]);
                sw += w0 + w1;
                wGa2[k] = pk(hg*0.5f*w0, hg*0.5f*w1);
            }
            cgG = hg*(0.5f*sw - P_acgof[l]);
            #pragma unroll
            for (int k = 0; k < 7; k++)
                wyG2[k] = pk(expf(P_lbcacg[l*NBC+2*k]), expf(P_lbcacg[l*NBC+2*k+1]));
        }
        // ---- Sec channel: A on lanes 16-25, H(=ACG 32-34) on lanes 0-2 ----
        uint64_t rS2p=0, nkSc2=0, kS12p=0, wyS2[7], wHa2[5];
        float cS=0.f, dkS=0.f;
        float* secPtr = ringA + 10*53;
        #pragma unroll
        for (int k = 0; k < 7; k++) wyS2[k] = 0;
        #pragma unroll
        for (int k = 0; k < 5; k++) wHa2[k] = 0;
        if (isA){
            int a = l - 16;
            float A,B,r1,r2,c1,c2;
            ac_coef(P_acltr[a], P_acltd[a], A,B,r1,r2,c1,c2);
            float ha = 0.5f*expf(P_aclsl[a]);
            float k1 = ha*A, k2 = ha*B;
            rS2p = pk(r1,r2); nkSc2 = pk(-k1*c1,-k2*c2); kS12p = pk(k1,k2);
            dkS = k1 - k2;
            cS = -ha*P_aclof[a];
            #pragma unroll
            for (int k = 0; k < 7; k++)
                wyS2[k] = pk(expf(P_lbcacl[a*NBC+2*k]), expf(P_lbcacl[a*NBC+2*k+1]));
            secPtr = ringA + a*53;
        } else if (isH){
            int h = l + 32;
            float A,B,r1,r2,c1,c2;
            ac_coef(P_acgtr[h], P_acgtd[h], A,B,r1,r2,c1,c2);
            float hh = 0.5f*expf(P_acgsl[h]);
            float k1 = hh*A, k2 = hh*B;
            rS2p = pk(r1,r2); nkSc2 = pk(-k1*c1,-k2*c2); kS12p = pk(k1,k2);
            dkS = k1 - k2;
            float swh = 0.f;
            #pragma unroll
            for (int k = 0; k < 5; k++){
                float w0 = -expf(P_laclacg[h*NACL+2*k]);
                float w1 = -expf(P_laclacg[h*NACL+2*k+1]);
                swh += w0 + w1;
                wHa2[k] = pk(hh*0.5f*w0, hh*0.5f*w1);
            }
            cS = hh*(0.5f*swh - P_acgof[h]);
            #pragma unroll
            for (int k = 0; k < 7; k++)
                wyS2[k] = pk(expf(P_lbcacg[h*NBC+2*k]), expf(P_lbcacg[h*NBC+2*k+1]));
            secPtr = ringG + h*53;
        }
        const int secSlot = isA ? (36 + (l-16)) : 46;
        const int hSlot   = isH ? (32 + l) : 46;
        // ---- BC feedback: 36 ACG taps (35+pad) + 10 ACL taps, prim lanes ----
        uint64_t wFB[18], wA2[5];
        #pragma unroll
        for (int k = 0; k < 18; k++) wFB[k] = 0;
        #pragma unroll
        for (int k = 0; k < 5; k++) wA2[k] = 0;
        if (prim){
            #pragma unroll
            for (int k = 0; k < 18; k++){
                int j0 = 2*k, j1 = 2*k+1;
                float w0 = (j0 < NACG) ? mh*(-expf(P_lacgbc[l*NACG+j0])) : 0.f;
                float w1 = (j1 < NACG) ? mh*(-expf(P_lacgbc[l*NACG+j1])) : 0.f;
                wFB[k] = pk(w0, w1);
            }
            #pragma unroll
            for (int k = 0; k < 5; k++){
                float w0 = -expf(P_laclbc[l*NACL+2*k]);
                float w1 = -expf(P_laclbc[l*NACL+2*k+1]);
                wA2[k] = pk(mh*w0, mh*w1);
            }
        }
        float* gRow = ringG + l*53;
        __syncwarp();

        uint64_t S12 = 0;
        float cvS = cS;
        /* carried state for relocated yG: rel regs, pbG, bDG, prev ring idx */
        uint64_t rp0c=0,rp1c=0,rp2c=0,rp3c=0,rp4c=0,rp5c=0,rp6c=0;
        uint64_t pbG_c = 0;
        float bDG_c = cgG;
        int ri_c = 0;
        { float tv0 = ftanh(cvS); sts32(sm_B + secSlot, tv0); }
        LOADCHUNK(0); STORECHUNK(0); LOADCHUNK(1);
        __syncwarp();
        for (int c = 0; c < NCHUNK; c++){
            int cur = c & 1;
            STORECHUNK(cur^1);
            int nk = (c+2 < NCHUNK) ? (c+2) : (NCHUNK-1);
            LOADCHUNK(nk);
            __syncwarp();
            const float* db = dbuf[cur];
            int tbase = c*16;
            #pragma unroll 2
            for (int i = 0; i < 16; i++){
                /* ---- head: tvA LDS opens; relocated yG fills its shadow ---- */
                uint64_t t0,t1,t2,t3,t4;
                ld128sv(sm_B+36, t0, t1);
                ld128sv(sm_B+40, t2, t3);
                t4 = ld64sv(sm_B+44);
                uint64_t ga = mul2(wyG2[0], rp0c);
                uint64_t gb = mul2(wyG2[1], rp1c);
                ga = fma2(wyG2[2], rp2c, ga);
                gb = fma2(wyG2[3], rp3c, gb);
                ga = fma2(wyG2[4], rp4c, ga);
                gb = fma2(wyG2[5], rp5c, gb);
                ga = fma2(wyG2[6], rp6c, ga);
                uint64_t gsum = add2(ga, gb);
                float gv0,gv1; upk(gsum,gv0,gv1);
                float yG = gv0+gv1;
                gRow[ri_c] = yG;
                uint64_t G12 = fma2(kG12p, pk(yG,yG), pbG_c);
                float baseG = fmaf(dkG, yG, bDG_c);
                /* ---- this step's top ---- */
                float yoS = secPtr[ri];
                float yoG = gRow[ri];
                float xi  = prim ? db[i*NBC + l] : 0.f;
                float fbBase = fmaf(mBC, xi, cP);
                float rrp_h = 0.5f*rrp;
                float t12 = c_p12*ip*(1.0f - rrp*c_irrp);
                float ip_n = ip + c_p01*(c_ipcap - ip) - t12;
                float rrp_m = rrp + t12;
                uint64_t pbS = fma2(nkSc2, pk(yoS,yoS), mul2(rS2p, S12));
                uint64_t pbG = fma2(nkGc2, pk(yoG,yoG), mul2(rG2p, G12));
                float b1,b2; upk(pbS,b1,b2); float bDS = (b1-b2)+cS;
                upk(pbG,b1,b2); float bDG = (b1-b2)+cgG;
                /* ---- stage 2, H FIRST: ph tree -> tanhH -> STS -> q16/q17 ---- */
                uint64_t ph0 = pk(cvS, 0.f);
                uint64_t ph1 = mul2(wHa2[1], t1);
                ph0 = fma2(wHa2[0], t0, ph0);
                ph1 = fma2(wHa2[2], t2, ph1);
                ph0 = fma2(wHa2[3], t3, ph0);
                ph1 = fma2(wHa2[4], t4, ph1);
                uint64_t phs = add2(ph0, ph1);
                float x0,x1;
                upk(phs,x0,x1);
                float tvH = ftanh(x0+x1);
                sts32(sm_B + hSlot, tvH);               /* converged */
                uint64_t q16,q17;
                ld128sv(sm_B+32, q16, q17);             /* only needs tvH commit */
                /* ---- then G: pg tree -> tanhG -> STS -> q0..q15 ---- */
                uint64_t pg0 = pk(baseG, 0.f);
                uint64_t pg1 = mul2(wGa2[1], t1);
                pg0 = fma2(wGa2[0], t0, pg0);
                pg1 = fma2(wGa2[2], t2, pg1);
                pg0 = fma2(wGa2[3], t3, pg0);
                pg1 = fma2(wGa2[4], t4, pg1);
                uint64_t pgs = add2(pg0, pg1);
                upk(pgs,x0,x1);
                float tvG = ftanh(x0+x1);
                sts32(sm_B + l, tvG);                   /* converged */
                uint64_t q0,q1,q2,q3,q4,q5,q6,q7,q8,q9,q10,q11,q12,q13,q14,q15;
                ld128sv(sm_B+0,  q0,  q1);
                ld128sv(sm_B+4,  q2,  q3);
                ld128sv(sm_B+8,  q4,  q5);
                ld128sv(sm_B+12, q6,  q7);
                ld128sv(sm_B+16, q8,  q9);
                ld128sv(sm_B+20, q10, q11);
                ld128sv(sm_B+24, q12, q13);
                ld128sv(sm_B+28, q14, q15);
                /* ACL->BC partials from t regs (fills the commit window) */
                uint64_t ae0 = mul2(wA2[0], t0);
                uint64_t ae1 = mul2(wA2[1], t1);
                ae0 = fma2(wA2[2], t2, ae0);
                ae1 = fma2(wA2[3], t3, ae1);
                ae0 = fma2(wA2[4], t4, ae0);
                /* ---- stage 3: q16/q17 folded EARLY; 18 packed taps, 4 accums ---- */
                uint64_t s0 = pk(fbBase, 0.f);
                s0 = fma2(wFB[16], q16, s0);
                uint64_t s1 = ae0;
                s1 = fma2(wFB[17], q17, s1);
                uint64_t s2 = ae1;
                uint64_t s3 = mul2(wFB[3], q3);
                s0 = fma2(wFB[0], q0, s0);
                s1 = fma2(wFB[1], q1, s1);
                s2 = fma2(wFB[2], q2, s2);
                s0 = fma2(wFB[4], q4, s0);
                s1 = fma2(wFB[5], q5, s1);
                s2 = fma2(wFB[6], q6, s2);
                s3 = fma2(wFB[7], q7, s3);
                s0 = fma2(wFB[8], q8, s0);
                s1 = fma2(wFB[9], q9, s1);
                s2 = fma2(wFB[10], q10, s2);
                s3 = fma2(wFB[11], q11, s3);
                s0 = fma2(wFB[12], q12, s0);
                s1 = fma2(wFB[13], q13, s1);
                s2 = fma2(wFB[14], q14, s2);
                s3 = fma2(wFB[15], q15, s3);
                uint64_t sv = add2(add2(s0,s1), add2(s2,s3));
                float u0,u1; upk(sv,u0,u1);
                float tvp = ftanh(u0+u1);
                float relv = fmaf(rrp_h, tvp, rrp_h);
                ip = ip_n; rrp = rrp_m - relv;
                sts32(sm_rel + relSlot, relv);          /* converged */
                if (prim) relrow[tbase+i] = relv;       /* divergent AFTER sts */
                /* ---- tail (K-best order: bookkeeping stores first, tvA STS last) ---- */
                uint64_t rpx;
                ld128sv(sm_rel+0, rp0c, rp1c);
                ld128sv(sm_rel+4, rp2c, rp3c);
                ld128sv(sm_rel+8, rp4c, rp5c);
                ld128sv(sm_rel+12, rp6c, rpx);
                uint64_t sa = mul2(wyS2[0], rp0c);
                uint64_t sb = mul2(wyS2[1], rp1c);
                sa = fma2(wyS2[2], rp2c, sa);
                sb = fma2(wyS2[3], rp3c, sb);
                sa = fma2(wyS2[4], rp4c, sa);
                sb = fma2(wyS2[5], rp5c, sb);
                sa = fma2(wyS2[6], rp6c, sa);
                uint64_t ss2 = add2(sa, sb);
                float v0,v1; upk(ss2,v0,v1);
                float yS = v0+v1;
                cvS = fmaf(dkS, yS, bDS);
                secPtr[ri] = yS;
                S12 = fma2(kS12p, pk(yS,yS), pbS);
                pbG_c = pbG; bDG_c = bDG; ri_c = ri;
                float tvS = ftanh(cvS);
                sts32(sm_B + secSlot, tvS);             /* LAST store before next head LDS */
                ri = (ri == KACN-1) ? 0 : ri+1;
            }
            __syncwarp();
        }
    }
#undef LOADCHUNK
#undef STORECHUNK
}

// ---------------- iGluSnFR readout: 32-tap FIR over rel ----------------
__global__ void out_kernel(float* __restrict__ out){
    __shared__ float skg[K1];
    int tid = threadIdx.x;
    if (tid < K1) skg[tid] = g_kglu[tid];
    __syncthreads();
    int oid = blockIdx.x*blockDim.x + tid;
    if (oid >= 2*NBC*TN) return;
    int n  = oid & (TN-1);
    int pc = oid >> 15;
    const float* r = g_rel + pc*RELSTRIDE + n;
    float a0 = 0.f, a1 = 0.f;
    #pragma unroll
    for (int j = 0; j < K1; j++){
        float v = r[K1-1-j];
        if (j & 1) a1 = fmaf(skg[j], v, a1);
        else       a0 = fmaf(skg[j], v, a0);
    }
    out[oid] = a0 + a1;
}

extern "C" void kernel_launch(void* const* d_in, const int* in_sizes, int n_in,
                              void* d_out, int out_size){
    (void)in_sizes; (void)n_in; (void)out_size;
    const float* x  = (const float*)d_in[0];
    const float* sb = (const float*)d_in[1];
    const float* ss = (const float*)d_in[2];

    setup_kernel<<<1, 64>>>((const float*)d_in[3]);
    xp_kernel<<<(XPLEN+255)/256, 256>>>(x, sb, ss);
    drive_kernel<<<(NSTEPS+127)/128, 128>>>();
    scan_kernel<<<2, 32>>>(
        (const float*)d_in[4],  (const float*)d_in[5],
        (const float*)d_in[6],  (const float*)d_in[7],
        (const float*)d_in[8],  (const float*)d_in[9],
        (const float*)d_in[10], (const float*)d_in[11],
        (const float*)d_in[12], (const float*)d_in[13],
        (const float*)d_in[14], (const float*)d_in[15],
        (const float*)d_in[16], (const float*)d_in[17],
        (const float*)d_in[18], (const float*)d_in[19],
        (const float*)d_in[20], (const float*)d_in[21],
        (const float*)d_in[22], (const float*)d_in[23],
        (const float*)d_in[24], (const float*)d_in[25]);
    out_kernel<<<(2*NBC*TN+255)/256, 256>>>((float*)d_out);
}